// round 7
// baseline (speedup 1.0000x reference)
#include <cuda_runtime.h>
#include <cuda_bf16.h>

// RoiAlign: fm (1,256,50,50) f32, proposals (1024,4) f32 -> out (1024,256,7,7) f32
// Reference double-applies SCALE => /256, roi_w/h clamped >=1, so every sample
// coord is in [0, 3.23]: all boxes read only fm[:, 0:5, 0:5]. Cache that 5x5
// patch per channel in registers (via a cooperative smem fill whose buffer is
// then REUSED as the store stage), and reuse it across GBOX boxes. Per-box the
// only varying data is the tiny separable weight tables Wy[7][5], Wx[7][5].
// Runtime-validated per box with a gmem fallback if a patch exceeds [0,4].

#define C_CH  256
#define HH    50
#define WW    50
#define OUTSZ 7
#define SSAMP 14    // OUT * SR
#define SPAN  5     // fixed patch 0..4 per axis
#define BTH   128   // threads = channels per block-half
#define GBOX  2     // boxes per block

__global__ __launch_bounds__(BTH, 8)
void roi_align_kernel(const float* __restrict__ fm,
                      const float* __restrict__ proposals,
                      float* __restrict__ out)
{
    const int tid  = threadIdx.x;
    const int half = blockIdx.y;
    const int n0   = blockIdx.x * GBOX;

    // s_buf: first the 5x5 hot patch (BTH*25 floats), then reused as the
    // 49-float/channel store stage (BTH*49 floats = 25088 B).
    __shared__ __align__(16) float s_buf[BTH * 49];
    __shared__ float s_h[GBOX * 2 * SSAMP], s_l[GBOX * 2 * SSAMP];
    __shared__ int   s_a0[GBOX * 2 * SSAMP], s_a1[GBOX * 2 * SSAMP];
    __shared__ float sWy[GBOX][OUTSZ][SPAN], sWx[GBOX][OUTSZ][SPAN];
    __shared__ int   s_ok[GBOX];

    // ---------- cooperative fill of hot fm patch into s_buf[ch*25+k] ----------
    {
        const float* fmh = fm + (size_t)(half * BTH) * (HH * WW);
        #pragma unroll 1
        for (int j = 0; j < 25; j++) {
            int i = j * BTH + tid;
            int ch = i / 25, k = i % 25;
            s_buf[i] = fmh[ch * (HH * WW) + (k / 5) * WW + (k % 5)];
        }
    }

    // ---------- per-box axis sample params: GBOX*28 = 56 threads ----------
    if (tid < GBOX * 2 * SSAMP) {
        const int g = tid / (2 * SSAMP);
        const int j = tid % (2 * SSAMP);
        const bool isY = j < SSAMP;
        const int  s   = isY ? j : j - SSAMP;
        float4 p = reinterpret_cast<const float4*>(proposals)[n0 + g];
        const float sc = 0.0625f;
        float x1 = (p.x * sc) * sc, y1v = (p.y * sc) * sc;
        float x2 = (p.z * sc) * sc, y2v = (p.w * sc) * sc;
        float roiw = fmaxf(x2 - x1, 1.0f);
        float roih = fmaxf(y2v - y1v, 1.0f);
        float gg = ((float)s + 0.5f) * 0.5f;              // (s+0.5)/SR
        float v = isY ? (y1v + (roih * (1.0f / 7.0f)) * gg)
                      : (x1  + (roiw * (1.0f / 7.0f)) * gg);
        const int L = HH;                                  // H == W == 50
        bool valid = (v >= -1.0f) && (v <= (float)L);
        float vc = fminf(fmaxf(v, 0.0f), (float)(L - 1));
        int i0 = min((int)floorf(vc), L - 1);
        int i1 = min(i0 + 1, L - 1);
        float l = vc - (float)i0;
        float h = 1.0f - l;
        if (!valid) { h = 0.0f; l = 0.0f; }
        s_a0[tid] = i0; s_a1[tid] = i1; s_h[tid] = h; s_l[tid] = l;
    }
    __syncthreads();

    // ---------- preload channel patch to regs; build weights in parallel ----------
    float r[25];
    #pragma unroll
    for (int k = 0; k < 25; k++) r[k] = s_buf[tid * 25 + k];

    if (tid < GBOX * 2 * OUTSZ) {          // GBOX*14 = 28 threads
        const int g = tid / (2 * OUTSZ);
        const int j = tid % (2 * OUTSZ);
        const bool isY = j < OUTSZ;
        const int  o   = isY ? j : j - OUTSZ;
        const int  off = g * 2 * SSAMP + (isY ? 0 : SSAMP);
        float w[SPAN] = {0.f, 0.f, 0.f, 0.f, 0.f};
        #pragma unroll
        for (int k = 0; k < 2; k++) {
            int s = off + 2 * o + k;
            w[min(s_a0[s], SPAN - 1)] += 0.5f * s_h[s];
            w[min(s_a1[s], SPAN - 1)] += 0.5f * s_l[s];
        }
        #pragma unroll
        for (int q = 0; q < SPAN; q++) {
            if (isY) sWy[g][o][q] = w[q]; else sWx[g][o][q] = w[q];
        }
    } else if (tid >= 64 && tid < 64 + GBOX) {
        const int g = tid - 64;
        int mx = -1;
        #pragma unroll
        for (int s = 0; s < 2 * SSAMP; s++)
            mx = max(mx, s_a1[g * 2 * SSAMP + s]);
        s_ok[g] = (mx <= SPAN - 1) ? 1 : 0;
    }
    __syncthreads();   // weights visible; ALL preloads done before stage overwrite

    const int c = half * BTH + tid;
    const float* fmc = fm + (size_t)c * (HH * WW);

    #pragma unroll 1
    for (int g = 0; g < GBOX; g++) {
        float* outb = out + (size_t)(n0 + g) * (C_CH * 49);
        if (s_ok[g]) {
            // row-major separable combine (low live-register count):
            // per oy: ty[x] = sum_y r[y][x]*Wy[oy][y]; out = sum_x ty[x]*Wx[ox][x]
            float* st = s_buf + tid * 49;
            #pragma unroll
            for (int oy = 0; oy < OUTSZ; oy++) {
                float wy0 = sWy[g][oy][0], wy1 = sWy[g][oy][1], wy2 = sWy[g][oy][2];
                float wy3 = sWy[g][oy][3], wy4 = sWy[g][oy][4];
                float ty0 = r[0]*wy0 + r[5]*wy1 + r[10]*wy2 + r[15]*wy3 + r[20]*wy4;
                float ty1 = r[1]*wy0 + r[6]*wy1 + r[11]*wy2 + r[16]*wy3 + r[21]*wy4;
                float ty2 = r[2]*wy0 + r[7]*wy1 + r[12]*wy2 + r[17]*wy3 + r[22]*wy4;
                float ty3 = r[3]*wy0 + r[8]*wy1 + r[13]*wy2 + r[18]*wy3 + r[23]*wy4;
                float ty4 = r[4]*wy0 + r[9]*wy1 + r[14]*wy2 + r[19]*wy3 + r[24]*wy4;
                #pragma unroll
                for (int ox = 0; ox < OUTSZ; ox++)
                    st[oy * 7 + ox] = ty0 * sWx[g][ox][0] + ty1 * sWx[g][ox][1]
                                    + ty2 * sWx[g][ox][2] + ty3 * sWx[g][ox][3]
                                    + ty4 * sWx[g][ox][4];
            }
        } else {
            // ---------- general fallback: direct gmem compute + store ----------
            float* outc = outb + (size_t)c * 49;
            const int off = g * 2 * SSAMP;
            for (int oy = 0; oy < OUTSZ; oy++) {
                for (int ox = 0; ox < OUTSZ; ox++) {
                    float a = 0.0f;
                    #pragma unroll
                    for (int ky = 0; ky < 2; ky++) {
                        int sy = off + 2 * oy + ky;
                        int y0 = s_a0[sy] * WW, y1i = s_a1[sy] * WW;
                        float hy = s_h[sy], ly = s_l[sy];
                        #pragma unroll
                        for (int kx = 0; kx < 2; kx++) {
                            int sxi = off + SSAMP + 2 * ox + kx;
                            int x0 = s_a0[sxi], x1i = s_a1[sxi];
                            float hx = s_h[sxi], lx = s_l[sxi];
                            a += hy * (hx * fmc[y0 + x0]  + lx * fmc[y0 + x1i])
                               + ly * (hx * fmc[y1i + x0] + lx * fmc[y1i + x1i]);
                        }
                    }
                    outc[oy * 7 + ox] = a * 0.25f;
                }
            }
        }
        __syncthreads();

        if (s_ok[g]) {
            // coalesced block store: 1568 float4 = 12*128 + 32
            float4* dst = reinterpret_cast<float4*>(outb + (size_t)half * (BTH * 49));
            const float4* src = reinterpret_cast<const float4*>(s_buf);
            #pragma unroll 4
            for (int it = 0; it < 12; it++)
                dst[it * BTH + tid] = src[it * BTH + tid];
            if (tid < 32)
                dst[12 * BTH + tid] = src[12 * BTH + tid];
        }
        __syncthreads();
    }
}

extern "C" void kernel_launch(void* const* d_in, const int* in_sizes, int n_in,
                              void* d_out, int out_size) {
    const float* fm    = (const float*)d_in[0];   // (1,256,50,50) f32
    const float* props = (const float*)d_in[1];   // (1024,4) f32
    float* out         = (float*)d_out;           // (1024,256,7,7) f32
    int N = in_sizes[1] / 4;
    dim3 grid(N / GBOX, 2);
    roi_align_kernel<<<grid, BTH>>>(fm, props, out);
}

// round 10
// speedup vs baseline: 1.2197x; 1.2197x over previous
#include <cuda_runtime.h>
#include <cuda_bf16.h>

// RoiAlign: fm (1,256,50,50) f32, proposals (1024,4) f32 -> out (1024,256,7,7) f32
// Reference double-applies SCALE => /256 and clamps roi_w/h >= 1, so every sample
// coord lies in [0, 3.23]: all boxes read only fm[:, 0:5, 0:5]. Cache that 5x5
// patch per channel in registers (cooperative smem fill; buffer then REUSED as
// the store stage) and reuse across GBOX boxes. Separable combine contracts x
// first (tx[7][5] in regs) so each smem weight is read exactly once per box.
// Staged results leave via a coalesced float4 block copy. Runtime-validated per
// box with a gmem fallback if a patch ever exceeds [0,4].

#define C_CH  256
#define HH    50
#define WW    50
#define OUTSZ 7
#define SSAMP 14    // OUT * SR
#define SPAN  5     // fixed patch 0..4 per axis
#define BTH   128   // threads = channels per block-half
#define GBOX  2     // boxes per block

__global__ __launch_bounds__(BTH)
void roi_align_kernel(const float* __restrict__ fm,
                      const float* __restrict__ proposals,
                      float* __restrict__ out)
{
    const int tid  = threadIdx.x;
    const int half = blockIdx.y;
    const int n0   = blockIdx.x * GBOX;

    // union buffer: first the hot patch (BTH*25), then the 49-float/ch stage.
    __shared__ __align__(16) float s_buf[BTH * 49];     // 25088 B
    __shared__ float s_h[GBOX * 2 * SSAMP], s_l[GBOX * 2 * SSAMP];
    __shared__ int   s_a0[GBOX * 2 * SSAMP], s_a1[GBOX * 2 * SSAMP];
    __shared__ float sWy[GBOX][OUTSZ][SPAN], sWx[GBOX][OUTSZ][SPAN];
    __shared__ int   s_ok[GBOX];

    // ---------- cooperative fill of hot fm patch into s_buf[ch*25+k] ----------
    {
        const float* fmh = fm + (size_t)(half * BTH) * (HH * WW);
        #pragma unroll 1
        for (int j = 0; j < 25; j++) {
            int i = j * BTH + tid;
            int ch = i / 25, k = i % 25;
            s_buf[i] = fmh[ch * (HH * WW) + (k / 5) * WW + (k % 5)];
        }
    }

    // ---------- per-box axis sample params: GBOX*28 = 56 threads ----------
    if (tid < GBOX * 2 * SSAMP) {
        const int g = tid / (2 * SSAMP);
        const int j = tid % (2 * SSAMP);
        const bool isY = j < SSAMP;
        const int  s   = isY ? j : j - SSAMP;
        float4 p = reinterpret_cast<const float4*>(proposals)[n0 + g];
        const float sc = 0.0625f;
        float x1 = (p.x * sc) * sc, y1v = (p.y * sc) * sc;
        float x2 = (p.z * sc) * sc, y2v = (p.w * sc) * sc;
        float roiw = fmaxf(x2 - x1, 1.0f);
        float roih = fmaxf(y2v - y1v, 1.0f);
        float gg = ((float)s + 0.5f) * 0.5f;              // (s+0.5)/SR
        float v = isY ? (y1v + (roih * (1.0f / 7.0f)) * gg)
                      : (x1  + (roiw * (1.0f / 7.0f)) * gg);
        const int L = HH;                                  // H == W == 50
        bool valid = (v >= -1.0f) && (v <= (float)L);
        float vc = fminf(fmaxf(v, 0.0f), (float)(L - 1));
        int i0 = min((int)floorf(vc), L - 1);
        int i1 = min(i0 + 1, L - 1);
        float l = vc - (float)i0;
        float h = 1.0f - l;
        if (!valid) { h = 0.0f; l = 0.0f; }
        s_a0[tid] = i0; s_a1[tid] = i1; s_h[tid] = h; s_l[tid] = l;
    }
    __syncthreads();

    // ---------- preload channel patch to regs; build weights in parallel ----------
    float r[25];
    #pragma unroll
    for (int k = 0; k < 25; k++) r[k] = s_buf[tid * 25 + k];

    if (tid < GBOX * 2 * OUTSZ) {          // GBOX*14 = 28 threads
        const int g = tid / (2 * OUTSZ);
        const int j = tid % (2 * OUTSZ);
        const bool isY = j < OUTSZ;
        const int  o   = isY ? j : j - OUTSZ;
        const int  off = g * 2 * SSAMP + (isY ? 0 : SSAMP);
        float w[SPAN] = {0.f, 0.f, 0.f, 0.f, 0.f};
        #pragma unroll
        for (int k = 0; k < 2; k++) {
            int s = off + 2 * o + k;
            w[min(s_a0[s], SPAN - 1)] += 0.5f * s_h[s];
            w[min(s_a1[s], SPAN - 1)] += 0.5f * s_l[s];
        }
        #pragma unroll
        for (int q = 0; q < SPAN; q++) {
            if (isY) sWy[g][o][q] = w[q]; else sWx[g][o][q] = w[q];
        }
    } else if (tid >= 64 && tid < 64 + GBOX) {
        const int g = tid - 64;
        int mx = -1;
        #pragma unroll
        for (int s = 0; s < 2 * SSAMP; s++)
            mx = max(mx, s_a1[g * 2 * SSAMP + s]);
        s_ok[g] = (mx <= SPAN - 1) ? 1 : 0;
    }
    __syncthreads();   // weights visible; all preloads done before stage overwrite

    const int c = half * BTH + tid;
    const float* fmc = fm + (size_t)c * (HH * WW);

    #pragma unroll 1
    for (int g = 0; g < GBOX; g++) {
        float* outb = out + (size_t)(n0 + g) * (C_CH * 49);

        if (s_ok[g]) {
            // ---- phase 1 (regs only): tx[ox][y] = sum_x r[y][x] * Wx[ox][x]
            //      each smem weight read exactly once ----
            float tx[OUTSZ][SPAN];
            #pragma unroll
            for (int ox = 0; ox < OUTSZ; ox++) {
                float w0 = sWx[g][ox][0], w1 = sWx[g][ox][1], w2 = sWx[g][ox][2];
                float w3 = sWx[g][ox][3], w4 = sWx[g][ox][4];
                #pragma unroll
                for (int y = 0; y < SPAN; y++)
                    tx[ox][y] = r[y*5+0]*w0 + r[y*5+1]*w1 + r[y*5+2]*w2
                              + r[y*5+3]*w3 + r[y*5+4]*w4;
            }

            // ---- phase 2: contract y, write straight to stage smem ----
            float* st = s_buf + tid * 49;
            #pragma unroll
            for (int oy = 0; oy < OUTSZ; oy++) {
                float wy0 = sWy[g][oy][0], wy1 = sWy[g][oy][1], wy2 = sWy[g][oy][2];
                float wy3 = sWy[g][oy][3], wy4 = sWy[g][oy][4];
                #pragma unroll
                for (int ox = 0; ox < OUTSZ; ox++)
                    st[oy * 7 + ox] = tx[ox][0]*wy0 + tx[ox][1]*wy1 + tx[ox][2]*wy2
                                    + tx[ox][3]*wy3 + tx[ox][4]*wy4;
            }
        } else {
            // ---------- general fallback: direct gmem compute + store ----------
            float* outc = outb + (size_t)c * 49;
            const int off = g * 2 * SSAMP;
            for (int oy = 0; oy < OUTSZ; oy++) {
                for (int ox = 0; ox < OUTSZ; ox++) {
                    float a = 0.0f;
                    #pragma unroll
                    for (int ky = 0; ky < 2; ky++) {
                        int sy = off + 2 * oy + ky;
                        int y0 = s_a0[sy] * WW, y1i = s_a1[sy] * WW;
                        float hy = s_h[sy], ly = s_l[sy];
                        #pragma unroll
                        for (int kx = 0; kx < 2; kx++) {
                            int sxi = off + SSAMP + 2 * ox + kx;
                            int x0 = s_a0[sxi], x1i = s_a1[sxi];
                            float hx = s_h[sxi], lx = s_l[sxi];
                            a += hy * (hx * fmc[y0 + x0]  + lx * fmc[y0 + x1i])
                               + ly * (hx * fmc[y1i + x0] + lx * fmc[y1i + x1i]);
                        }
                    }
                    outc[oy * 7 + ox] = a * 0.25f;
                }
            }
        }
        __syncthreads();

        if (s_ok[g]) {
            // ---- coalesced block store: 1568 float4 = 12*128 + 32 ----
            float4* dst = reinterpret_cast<float4*>(outb + (size_t)half * (BTH * 49));
            const float4* src = reinterpret_cast<const float4*>(s_buf);
            #pragma unroll 4
            for (int it = 0; it < 12; it++)
                dst[it * BTH + tid] = src[it * BTH + tid];
            if (tid < 32)
                dst[12 * BTH + tid] = src[12 * BTH + tid];
        }
        __syncthreads();
    }
}

extern "C" void kernel_launch(void* const* d_in, const int* in_sizes, int n_in,
                              void* d_out, int out_size) {
    const float* fm    = (const float*)d_in[0];   // (1,256,50,50) f32
    const float* props = (const float*)d_in[1];   // (1024,4) f32
    float* out         = (float*)d_out;           // (1024,256,7,7) f32
    int N = in_sizes[1] / 4;
    dim3 grid(N / GBOX, 2);
    roi_align_kernel<<<grid, BTH>>>(fm, props, out);
}